// round 12
// baseline (speedup 1.0000x reference)
#include <cuda_runtime.h>
#include <cuda_bf16.h>
#include <cstdint>
#include <cstddef>

// Problem constants
#define PB  4
#define PT  4096
#define PD  2048
#define PM  512
#define PBT (PB*PT)          // 16384
#define PKG (PD+PM)          // 2560
#define NCH 64               // chunks over T
#define CHL 64               // chunk length (NCH*CHL == PT)

// ---------------- scratch (no allocation allowed) ----------------
__device__ float g_v[(size_t)PBT * PM];                 // value projection [BT, M] fp32
__device__ float g_chsum [PB * NCH * PM];
__device__ float g_prefix[PB * NCH * PM];
// bf16 hi/lo splits
__device__ __nv_bfloat16 g_xh [(size_t)PBT * PD];
__device__ __nv_bfloat16 g_xl [(size_t)PBT * PD];
__device__ __nv_bfloat16 g_wvh[(size_t)PBT * PM];
__device__ __nv_bfloat16 g_wvl[(size_t)PBT * PM];
__device__ __nv_bfloat16 g_Wvh[(size_t)PM * PD];
__device__ __nv_bfloat16 g_Wvl[(size_t)PM * PD];
__device__ __nv_bfloat16 g_Wgh[(size_t)PD * PKG];
__device__ __nv_bfloat16 g_Wgl[(size_t)PD * PKG];

__device__ __forceinline__ float sigmoid_f(float x) {
    return 1.0f / (1.0f + expf(-x));
}

// ---------------- PTX helpers (sm_80-era ISA only; no tcgen05) ----------------
__device__ __forceinline__ uint32_t smem_u32(const void* p) {
    uint32_t a;
    asm("{ .reg .u64 t; cvta.to.shared.u64 t, %1; cvt.u32.u64 %0, t; }"
        : "=r"(a) : "l"(p));
    return a;
}
__device__ __forceinline__ void cp_async16(uint32_t dst, const void* src) {
    asm volatile("cp.async.cg.shared.global [%0], [%1], 16;"
                 :: "r"(dst), "l"(src) : "memory");
}
__device__ __forceinline__ void ldsm4(uint32_t& r0, uint32_t& r1,
                                      uint32_t& r2, uint32_t& r3, uint32_t addr) {
    asm volatile("ldmatrix.sync.aligned.m8n8.x4.shared.b16 {%0,%1,%2,%3}, [%4];"
                 : "=r"(r0), "=r"(r1), "=r"(r2), "=r"(r3) : "r"(addr));
}
__device__ __forceinline__ void mma16816(float* c, const uint32_t* a, const uint32_t* b) {
    asm volatile(
        "mma.sync.aligned.m16n8k16.row.col.f32.bf16.bf16.f32 "
        "{%0,%1,%2,%3}, {%4,%5,%6,%7}, {%8,%9}, {%0,%1,%2,%3};"
        : "+f"(c[0]), "+f"(c[1]), "+f"(c[2]), "+f"(c[3])
        : "r"(a[0]), "r"(a[1]), "r"(a[2]), "r"(a[3]), "r"(b[0]), "r"(b[1]));
}

// ---------------- split-bf16 mma.sync GEMM ----------------
// C[r,c] = (resid? resid[r,c]:0) + bias[c] + sum_k A(r,k)*W[c,k]  (fp32 result),
// A and W given as (hi, lo) bf16 splits; computes hh + hl + lh.
// A(r,k) = A1 for k<K1 (row stride K1) else A2 (row stride K2).
// CTA tile 128x128, BK=32; smem row = [hi 64B | lo 64B] = 128B, XOR-8 swizzle.
// KEY: the 3 term-passes are issued as 3 x 16 INDEPENDENT MMAs (term loop
// outermost) so no back-to-back RAW on an accumulator ever reaches the pipe.
#define STAGE_BYTES 32768      // A(128*128B) + B(128*128B)
#define SMEM_TOTAL  (3*STAGE_BYTES)

__global__ __launch_bounds__(256, 1)
void gemm_mma(const __nv_bfloat16* __restrict__ A1h, const __nv_bfloat16* __restrict__ A1l,
              int K1,
              const __nv_bfloat16* __restrict__ A2h, const __nv_bfloat16* __restrict__ A2l,
              int K2,
              const __nv_bfloat16* __restrict__ Wh,  const __nv_bfloat16* __restrict__ Wl,
              const float* __restrict__ bias, const float* __restrict__ resid,
              float* __restrict__ C)
{
    extern __shared__ char smem[];
    const uint32_t sbase = smem_u32(smem);
    const int tid  = threadIdx.x;
    const int lane = tid & 31;
    const int warp = tid >> 5;
    const int m0 = (warp & 1) * 64;    // warp grid 2(M) x 4(N)
    const int n0 = (warp >> 1) * 32;
    const int rowBase = blockIdx.y * 128;
    const int colBase = blockIdx.x * 128;
    const int Nout = gridDim.x * 128;
    const int Ktot = K1 + K2;
    const int ntiles = Ktot / 32;

    // loader mapping: 2 threads per row (hi/lo half), 4x 16B chunks each
    const int lr = tid >> 1;       // row 0..127
    const int lh = tid & 1;        // 0 = hi half, 1 = lo half

    auto load_tile = [&](int stage, int kt) {
        const int k0 = kt * 32;
        const __nv_bfloat16 *Ah, *Al; int lda, kc;
        if (k0 < K1) { Ah = A1h; Al = A1l; lda = K1; kc = k0; }
        else         { Ah = A2h; Al = A2l; lda = K2; kc = k0 - K1; }
        const __nv_bfloat16* ga = (lh ? Al : Ah) + (size_t)(rowBase + lr) * lda + kc;
        const __nv_bfloat16* gb = (lh ? Wl : Wh) + (size_t)(colBase + lr) * Ktot + k0;
        const uint32_t sa = sbase + stage * STAGE_BYTES + lr * 128;
        const uint32_t sb = sa + 16384;
#pragma unroll
        for (int g = 0; g < 4; g++) {
            const uint32_t slot = (uint32_t)((g + lh * 4) ^ (lr & 7));
            cp_async16(sa + slot * 16, ga + g * 8);
            cp_async16(sb + slot * 16, gb + g * 8);
        }
    };

    load_tile(0, 0);
    asm volatile("cp.async.commit_group;" ::: "memory");
    load_tile(1, 1);
    asm volatile("cp.async.commit_group;" ::: "memory");

    float acc[4][4][4];
#pragma unroll
    for (int mt = 0; mt < 4; mt++)
#pragma unroll
        for (int nt = 0; nt < 4; nt++)
#pragma unroll
            for (int e = 0; e < 4; e++) acc[mt][nt][e] = 0.0f;

    const int li = lane >> 3;      // ldmatrix matrix index 0..3
    const int lj = lane & 7;       // row within 8x8 matrix

    for (int kt = 0; kt < ntiles; kt++) {
        asm volatile("cp.async.wait_group 1;" ::: "memory");
        __syncthreads();           // stage kt ready; everyone done with stage kt-1

        if (kt + 2 < ntiles) load_tile((kt + 2) % 3, kt + 2);
        asm volatile("cp.async.commit_group;" ::: "memory");

        const uint32_t aB = sbase + (kt % 3) * STAGE_BYTES;
        const uint32_t bB = aB + 16384;

#pragma unroll
        for (int ks = 0; ks < 2; ks++) {
            uint32_t a[2][4][4];   // [term hi/lo][m16 tile][4 regs]
            uint32_t b[2][4][2];   // [term hi/lo][n8 tile][2 regs]
            // Load ALL fragments for this ks first (LDSM overlaps prior MMAs)
#pragma unroll
            for (int h = 0; h < 2; h++)
#pragma unroll
                for (int mt = 0; mt < 4; mt++) {
                    const int row = m0 + mt * 16 + (li & 1) * 8 + lj;
                    const int g   = 2 * ks + (li >> 1) + h * 4;
                    const uint32_t ad = aB + row * 128 + ((uint32_t)(g ^ (row & 7))) * 16;
                    ldsm4(a[h][mt][0], a[h][mt][1], a[h][mt][2], a[h][mt][3], ad);
                }
#pragma unroll
            for (int h = 0; h < 2; h++)
#pragma unroll
                for (int np = 0; np < 2; np++) {
                    const int row = n0 + np * 16 + (li >> 1) * 8 + lj;
                    const int g   = 2 * ks + (li & 1) + h * 4;
                    const uint32_t bd = bB + row * 128 + ((uint32_t)(g ^ (row & 7))) * 16;
                    uint32_t r0, r1, r2, r3;
                    ldsm4(r0, r1, r2, r3, bd);
                    b[h][np * 2 + 0][0] = r0; b[h][np * 2 + 0][1] = r1;
                    b[h][np * 2 + 1][0] = r2; b[h][np * 2 + 1][1] = r3;
                }
            // 3 passes of 16 independent MMAs: accumulator reuse distance = 16
#pragma unroll
            for (int p = 0; p < 3; p++) {
                const int ha = (p == 2) ? 1 : 0;   // hh, hl, lh
                const int hb = (p == 1) ? 1 : 0;
#pragma unroll
                for (int mt = 0; mt < 4; mt++)
#pragma unroll
                    for (int nt = 0; nt < 4; nt++)
                        mma16816(acc[mt][nt], a[ha][mt], b[hb][nt]);
            }
        }
    }

    // Epilogue: c0,c1 @ (row lane/4, col (lane%4)*2); c2,c3 @ row+8
    const int er = lane >> 2;
    const int ec = (lane & 3) * 2;
#pragma unroll
    for (int mt = 0; mt < 4; mt++) {
        const int r0g = rowBase + m0 + mt * 16 + er;
#pragma unroll
        for (int nt = 0; nt < 4; nt++) {
            const int cg = colBase + n0 + nt * 8 + ec;
            const float2 bb = *(const float2*)(bias + cg);
            float2 v0 = make_float2(acc[mt][nt][0] + bb.x, acc[mt][nt][1] + bb.y);
            float2 v1 = make_float2(acc[mt][nt][2] + bb.x, acc[mt][nt][3] + bb.y);
            if (resid) {
                const float2 rA = *(const float2*)(resid + (size_t)r0g * Nout + cg);
                const float2 rB = *(const float2*)(resid + (size_t)(r0g + 8) * Nout + cg);
                v0.x += rA.x; v0.y += rA.y; v1.x += rB.x; v1.y += rB.y;
            }
            *(float2*)(C + (size_t)r0g * Nout + cg)       = v0;
            *(float2*)(C + (size_t)(r0g + 8) * Nout + cg) = v1;
        }
    }
}

// ---------------- fp32 -> (hi, lo) bf16 split ----------------
__global__ void split_fp32(const float4* __restrict__ src,
                           __nv_bfloat162* __restrict__ hi,
                           __nv_bfloat162* __restrict__ lo, int n4)
{
    const int i = blockIdx.x * blockDim.x + threadIdx.x;
    if (i >= n4) return;
    const float4 v = src[i];
    const __nv_bfloat16 hx = __float2bfloat16(v.x);
    const __nv_bfloat16 hy = __float2bfloat16(v.y);
    const __nv_bfloat16 hz = __float2bfloat16(v.z);
    const __nv_bfloat16 hw = __float2bfloat16(v.w);
    const __nv_bfloat16 lx = __float2bfloat16(v.x - __bfloat162float(hx));
    const __nv_bfloat16 ly = __float2bfloat16(v.y - __bfloat162float(hy));
    const __nv_bfloat16 lz = __float2bfloat16(v.z - __bfloat162float(hz));
    const __nv_bfloat16 lw = __float2bfloat16(v.w - __bfloat162float(hw));
    hi[2 * i + 0] = __nv_bfloat162(hx, hy);
    hi[2 * i + 1] = __nv_bfloat162(hz, hw);
    lo[2 * i + 0] = __nv_bfloat162(lx, ly);
    lo[2 * i + 1] = __nv_bfloat162(lz, lw);
}

// ---------------- recurrence as a blocked linear scan ----------------
__global__ void recur_chunk_sum(const float* __restrict__ time_decay)
{
    const int idx = blockIdx.x * blockDim.x + threadIdx.x;
    const int m  = idx & (PM - 1);
    const int ch = (idx >> 9) & (NCH - 1);
    const int b  = idx >> 15;
    const float decay = sigmoid_f(time_decay[m]) * 0.9f + 0.1f;
    const float* vp = g_v + ((size_t)(b * PT + ch * CHL)) * PM + m;
    float s = 0.0f;
#pragma unroll 8
    for (int j = 0; j < CHL; j++)
        s = fmaf(s, decay, vp[(size_t)j * PM]);
    g_chsum[(b * NCH + ch) * PM + m] = s;
}

__global__ void recur_prefix(const float* __restrict__ time_decay,
                             const float* __restrict__ mem0,
                             float* __restrict__ next_mem)
{
    const int idx = blockIdx.x * blockDim.x + threadIdx.x;
    const int m = idx & (PM - 1);
    const int b = idx >> 9;
    const float decay = sigmoid_f(time_decay[m]) * 0.9f + 0.1f;
    float A = decay;
#pragma unroll
    for (int i = 0; i < 6; i++) A = A * A;   // decay^64
    float P = mem0[b * PM + m];
#pragma unroll 4
    for (int ch = 0; ch < NCH; ch++) {
        g_prefix[(b * NCH + ch) * PM + m] = P;
        P = fmaf(P, A, g_chsum[(b * NCH + ch) * PM + m]);
    }
    if (next_mem) next_mem[b * PM + m] = P;
}

__global__ void recur_emit(const float* __restrict__ time_decay,
                           const float* __restrict__ time_first)
{
    const int idx = blockIdx.x * blockDim.x + threadIdx.x;
    const int m  = idx & (PM - 1);
    const int ch = (idx >> 9) & (NCH - 1);
    const int b  = idx >> 15;
    const float decay = sigmoid_f(time_decay[m]) * 0.9f + 0.1f;
    const float first = sigmoid_f(time_first[m]);
    const size_t base = ((size_t)(b * PT + ch * CHL)) * PM + m;
    const float* vp = g_v + base;
    float s = g_prefix[(b * NCH + ch) * PM + m];
#pragma unroll 8
    for (int j = 0; j < CHL; j++) {
        const float v = vp[(size_t)j * PM];
        const float wvv = fmaf(s, first, v);
        const __nv_bfloat16 h = __float2bfloat16(wvv);
        g_wvh[base + (size_t)j * PM] = h;
        g_wvl[base + (size_t)j * PM] = __float2bfloat16(wvv - __bfloat162float(h));
        s = fmaf(s, decay, v);
    }
}

// ---------------- launch ----------------
extern "C" void kernel_launch(void* const* d_in, const int* in_sizes, int n_in,
                              void* d_out, int out_size)
{
    const float* x    = (const float*)d_in[0];   // [B, T, D]
    const float* mem0 = (const float*)d_in[1];   // [B, M]
    const float* Wv   = (const float*)d_in[2];   // [M, D]
    const float* bv   = (const float*)d_in[3];   // [M]
    const float* Wg   = (const float*)d_in[4];   // [D, D+M]
    const float* bg   = (const float*)d_in[5];   // [D]
    const float* td   = (const float*)d_in[6];   // [M]
    const float* tf   = (const float*)d_in[7];   // [M]
    float* out = (float*)d_out;

    void *pv, *pxh, *pxl, *pwvh, *pwvl, *pWvh, *pWvl, *pWgh, *pWgl;
    cudaGetSymbolAddress(&pv,   g_v);
    cudaGetSymbolAddress(&pxh,  g_xh);
    cudaGetSymbolAddress(&pxl,  g_xl);
    cudaGetSymbolAddress(&pwvh, g_wvh);
    cudaGetSymbolAddress(&pwvl, g_wvl);
    cudaGetSymbolAddress(&pWvh, g_Wvh);
    cudaGetSymbolAddress(&pWvl, g_Wvl);
    cudaGetSymbolAddress(&pWgh, g_Wgh);
    cudaGetSymbolAddress(&pWgl, g_Wgl);

    cudaFuncSetAttribute(gemm_mma, cudaFuncAttributeMaxDynamicSharedMemorySize, SMEM_TOTAL);

    // fp32 -> bf16 hi/lo splits
    {
        int n4 = (PBT * PD) / 4;   // x
        split_fp32<<<(n4 + 255) / 256, 256>>>((const float4*)x,
            (__nv_bfloat162*)pxh, (__nv_bfloat162*)pxl, n4);
        n4 = (PM * PD) / 4;        // Wv
        split_fp32<<<(n4 + 255) / 256, 256>>>((const float4*)Wv,
            (__nv_bfloat162*)pWvh, (__nv_bfloat162*)pWvl, n4);
        n4 = (PD * PKG) / 4;       // Wg
        split_fp32<<<(n4 + 255) / 256, 256>>>((const float4*)Wg,
            (__nv_bfloat162*)pWgh, (__nv_bfloat162*)pWgl, n4);
    }

    // GEMM1: v[BT, M] = x . Wv^T + bv   (tensor cores, split-bf16)
    {
        dim3 grid(PM / 128, PBT / 128);   // (4, 128)
        gemm_mma<<<grid, 256, SMEM_TOTAL>>>(
            (const __nv_bfloat16*)pxh, (const __nv_bfloat16*)pxl, PD,
            nullptr, nullptr, 0,
            (const __nv_bfloat16*)pWvh, (const __nv_bfloat16*)pWvl,
            bv, nullptr, (float*)pv);
    }

    // Recurrence (blocked scan); emit wv directly as bf16 hi/lo
    recur_chunk_sum<<<(PB * NCH * PM) / 256, 256>>>(td);
    float* next_mem = nullptr;
    if (out_size >= (int)((size_t)PBT * PD + (size_t)PB * PM))
        next_mem = out + (size_t)PBT * PD;
    recur_prefix<<<(PB * PM) / 256, 256>>>(td, mem0, next_mem);
    recur_emit<<<(PB * NCH * PM) / 256, 256>>>(td, tf);

    // GEMM2: out[BT, D] = x + [x | wv] . Wg^T + bg
    {
        dim3 grid(PD / 128, PBT / 128);   // (16, 128)
        gemm_mma<<<grid, 256, SMEM_TOTAL>>>(
            (const __nv_bfloat16*)pxh, (const __nv_bfloat16*)pxl, PD,
            (const __nv_bfloat16*)pwvh, (const __nv_bfloat16*)pwvl, PM,
            (const __nv_bfloat16*)pWgh, (const __nv_bfloat16*)pWgl,
            bg, x, out);
    }
}

// round 17
// speedup vs baseline: 1.1425x; 1.1425x over previous
#include <cuda_runtime.h>
#include <cuda_bf16.h>
#include <cstdint>
#include <cstddef>

// Problem constants
#define PB  4
#define PT  4096
#define PD  2048
#define PM  512
#define PBT (PB*PT)          // 16384
#define PKG (PD+PM)          // 2560
#define NCH 64               // chunks over T
#define CHL 64               // chunk length (NCH*CHL == PT)

// ---------------- scratch (no allocation allowed) ----------------
__device__ float g_v[(size_t)PBT * PM];                 // value projection [BT, M] fp32
__device__ float g_chsum [PB * NCH * PM];
__device__ float g_prefix[PB * NCH * PM];
// bf16 hi/lo splits
__device__ __nv_bfloat16 g_xh [(size_t)PBT * PD];
__device__ __nv_bfloat16 g_xl [(size_t)PBT * PD];
__device__ __nv_bfloat16 g_wvh[(size_t)PBT * PM];
__device__ __nv_bfloat16 g_wvl[(size_t)PBT * PM];
__device__ __nv_bfloat16 g_Wvh[(size_t)PM * PD];
__device__ __nv_bfloat16 g_Wvl[(size_t)PM * PD];
__device__ __nv_bfloat16 g_Wgh[(size_t)PD * PKG];
__device__ __nv_bfloat16 g_Wgl[(size_t)PD * PKG];

__device__ __forceinline__ float sigmoid_f(float x) {
    return 1.0f / (1.0f + expf(-x));
}

// ---------------- PTX helpers (sm_80-era ISA only; no tcgen05) ----------------
__device__ __forceinline__ uint32_t smem_u32(const void* p) {
    uint32_t a;
    asm("{ .reg .u64 t; cvta.to.shared.u64 t, %1; cvt.u32.u64 %0, t; }"
        : "=r"(a) : "l"(p));
    return a;
}
__device__ __forceinline__ void cp_async16(uint32_t dst, const void* src) {
    asm volatile("cp.async.cg.shared.global [%0], [%1], 16;"
                 :: "r"(dst), "l"(src) : "memory");
}
__device__ __forceinline__ void ldsm4(uint32_t& r0, uint32_t& r1,
                                      uint32_t& r2, uint32_t& r3, uint32_t addr) {
    asm volatile("ldmatrix.sync.aligned.m8n8.x4.shared.b16 {%0,%1,%2,%3}, [%4];"
                 : "=r"(r0), "=r"(r1), "=r"(r2), "=r"(r3) : "r"(addr));
}
__device__ __forceinline__ void mma16816(float* c, const uint32_t* a, const uint32_t* b) {
    asm volatile(
        "mma.sync.aligned.m16n8k16.row.col.f32.bf16.bf16.f32 "
        "{%0,%1,%2,%3}, {%4,%5,%6,%7}, {%8,%9}, {%0,%1,%2,%3};"
        : "+f"(c[0]), "+f"(c[1]), "+f"(c[2]), "+f"(c[3])
        : "r"(a[0]), "r"(a[1]), "r"(a[2]), "r"(a[3]), "r"(b[0]), "r"(b[1]));
}

// ---------------- split-bf16 mma.sync GEMM ----------------
// C[r,c] = (resid? resid[r,c]:0) + bias[c] + sum_k A(r,k)*W[c,k]  (fp32 result),
// A and W given as (hi, lo) bf16 splits; computes hh + hl + lh.
// A(r,k) = A1 for k<K1 (row stride K1) else A2 (row stride K2).
// CTA tile 128x128, BK=32; smem row = [hi 64B | lo 64B] = 128B, XOR-8 swizzle.
// 2 CTAs/SM (launch_bounds reg cap 128): cross-CTA overlap hides LDSM/MMA
// latency and barrier bubbles that a single 8-warp CTA cannot cover.
// Per-ks register economy: a-frags loaded as hi, used for hh+hl passes, then
// RELOADED in-place as lo for the lh pass (live frags 48 -> 32 regs).
#define STAGE_BYTES 32768      // A(128*128B) + B(128*128B)
#define SMEM_TOTAL  (3*STAGE_BYTES)

__global__ __launch_bounds__(256, 2)
void gemm_mma(const __nv_bfloat16* __restrict__ A1h, const __nv_bfloat16* __restrict__ A1l,
              int K1,
              const __nv_bfloat16* __restrict__ A2h, const __nv_bfloat16* __restrict__ A2l,
              int K2,
              const __nv_bfloat16* __restrict__ Wh,  const __nv_bfloat16* __restrict__ Wl,
              const float* __restrict__ bias, const float* __restrict__ resid,
              float* __restrict__ C)
{
    extern __shared__ char smem[];
    const uint32_t sbase = smem_u32(smem);
    const int tid  = threadIdx.x;
    const int lane = tid & 31;
    const int warp = tid >> 5;
    const int m0 = (warp & 1) * 64;    // warp grid 2(M) x 4(N)
    const int n0 = (warp >> 1) * 32;
    const int rowBase = blockIdx.y * 128;
    const int colBase = blockIdx.x * 128;
    const int Nout = gridDim.x * 128;
    const int Ktot = K1 + K2;
    const int ntiles = Ktot / 32;

    // loader mapping: 2 threads per row (hi/lo half), 4x 16B chunks each
    const int lr = tid >> 1;       // row 0..127
    const int lh = tid & 1;        // 0 = hi half, 1 = lo half

    auto load_tile = [&](int stage, int kt) {
        const int k0 = kt * 32;
        const __nv_bfloat16 *Ah, *Al; int lda, kc;
        if (k0 < K1) { Ah = A1h; Al = A1l; lda = K1; kc = k0; }
        else         { Ah = A2h; Al = A2l; lda = K2; kc = k0 - K1; }
        const __nv_bfloat16* ga = (lh ? Al : Ah) + (size_t)(rowBase + lr) * lda + kc;
        const __nv_bfloat16* gb = (lh ? Wl : Wh) + (size_t)(colBase + lr) * Ktot + k0;
        const uint32_t sa = sbase + stage * STAGE_BYTES + lr * 128;
        const uint32_t sb = sa + 16384;
#pragma unroll
        for (int g = 0; g < 4; g++) {
            const uint32_t slot = (uint32_t)((g + lh * 4) ^ (lr & 7));
            cp_async16(sa + slot * 16, ga + g * 8);
            cp_async16(sb + slot * 16, gb + g * 8);
        }
    };

    load_tile(0, 0);
    asm volatile("cp.async.commit_group;" ::: "memory");
    load_tile(1, 1);
    asm volatile("cp.async.commit_group;" ::: "memory");

    float acc[4][4][4];
#pragma unroll
    for (int mt = 0; mt < 4; mt++)
#pragma unroll
        for (int nt = 0; nt < 4; nt++)
#pragma unroll
            for (int e = 0; e < 4; e++) acc[mt][nt][e] = 0.0f;

    const int li = lane >> 3;      // ldmatrix matrix index 0..3
    const int lj = lane & 7;       // row within 8x8 matrix

    for (int kt = 0; kt < ntiles; kt++) {
        asm volatile("cp.async.wait_group 1;" ::: "memory");
        __syncthreads();           // stage kt ready; everyone done with stage kt-1

        if (kt + 2 < ntiles) load_tile((kt + 2) % 3, kt + 2);
        asm volatile("cp.async.commit_group;" ::: "memory");

        const uint32_t aB = sbase + (kt % 3) * STAGE_BYTES;
        const uint32_t bB = aB + 16384;

#pragma unroll
        for (int ks = 0; ks < 2; ks++) {
            uint32_t a[4][4];              // reused: hi first, then lo
            uint32_t bh[4][2], bl[4][2];
            // a <- A_hi fragments
#pragma unroll
            for (int mt = 0; mt < 4; mt++) {
                const int row = m0 + mt * 16 + (li & 1) * 8 + lj;
                const int g   = 2 * ks + (li >> 1);
                const uint32_t ad = aB + row * 128 + ((uint32_t)(g ^ (row & 7))) * 16;
                ldsm4(a[mt][0], a[mt][1], a[mt][2], a[mt][3], ad);
            }
            // B hi and lo fragments
#pragma unroll
            for (int h = 0; h < 2; h++)
#pragma unroll
                for (int np = 0; np < 2; np++) {
                    const int row = n0 + np * 16 + (li >> 1) * 8 + lj;
                    const int g   = 2 * ks + (li & 1) + h * 4;
                    const uint32_t bd = bB + row * 128 + ((uint32_t)(g ^ (row & 7))) * 16;
                    uint32_t r0, r1, r2, r3;
                    ldsm4(r0, r1, r2, r3, bd);
                    if (h == 0) {
                        bh[np * 2 + 0][0] = r0; bh[np * 2 + 0][1] = r1;
                        bh[np * 2 + 1][0] = r2; bh[np * 2 + 1][1] = r3;
                    } else {
                        bl[np * 2 + 0][0] = r0; bl[np * 2 + 0][1] = r1;
                        bl[np * 2 + 1][0] = r2; bl[np * 2 + 1][1] = r3;
                    }
                }
            // pass 1: hi*hi ; pass 2: hi*lo
#pragma unroll
            for (int mt = 0; mt < 4; mt++)
#pragma unroll
                for (int nt = 0; nt < 4; nt++)
                    mma16816(acc[mt][nt], a[mt], bh[nt]);
#pragma unroll
            for (int mt = 0; mt < 4; mt++)
#pragma unroll
                for (int nt = 0; nt < 4; nt++)
                    mma16816(acc[mt][nt], a[mt], bl[nt]);
            // a <- A_lo fragments (in-place reload), pass 3: lo*hi
#pragma unroll
            for (int mt = 0; mt < 4; mt++) {
                const int row = m0 + mt * 16 + (li & 1) * 8 + lj;
                const int g   = 2 * ks + (li >> 1) + 4;
                const uint32_t ad = aB + row * 128 + ((uint32_t)(g ^ (row & 7))) * 16;
                ldsm4(a[mt][0], a[mt][1], a[mt][2], a[mt][3], ad);
            }
#pragma unroll
            for (int mt = 0; mt < 4; mt++)
#pragma unroll
                for (int nt = 0; nt < 4; nt++)
                    mma16816(acc[mt][nt], a[mt], bh[nt]);
        }
    }

    // Epilogue: c0,c1 @ (row lane/4, col (lane%4)*2); c2,c3 @ row+8
    const int er = lane >> 2;
    const int ec = (lane & 3) * 2;
#pragma unroll
    for (int mt = 0; mt < 4; mt++) {
        const int r0g = rowBase + m0 + mt * 16 + er;
#pragma unroll
        for (int nt = 0; nt < 4; nt++) {
            const int cg = colBase + n0 + nt * 8 + ec;
            const float2 bb = *(const float2*)(bias + cg);
            float2 v0 = make_float2(acc[mt][nt][0] + bb.x, acc[mt][nt][1] + bb.y);
            float2 v1 = make_float2(acc[mt][nt][2] + bb.x, acc[mt][nt][3] + bb.y);
            if (resid) {
                const float2 rA = *(const float2*)(resid + (size_t)r0g * Nout + cg);
                const float2 rB = *(const float2*)(resid + (size_t)(r0g + 8) * Nout + cg);
                v0.x += rA.x; v0.y += rA.y; v1.x += rB.x; v1.y += rB.y;
            }
            *(float2*)(C + (size_t)r0g * Nout + cg)       = v0;
            *(float2*)(C + (size_t)(r0g + 8) * Nout + cg) = v1;
        }
    }
}

// ---------------- fp32 -> (hi, lo) bf16 split ----------------
__global__ void split_fp32(const float4* __restrict__ src,
                           __nv_bfloat162* __restrict__ hi,
                           __nv_bfloat162* __restrict__ lo, int n4)
{
    const int i = blockIdx.x * blockDim.x + threadIdx.x;
    if (i >= n4) return;
    const float4 v = src[i];
    const __nv_bfloat16 hx = __float2bfloat16(v.x);
    const __nv_bfloat16 hy = __float2bfloat16(v.y);
    const __nv_bfloat16 hz = __float2bfloat16(v.z);
    const __nv_bfloat16 hw = __float2bfloat16(v.w);
    const __nv_bfloat16 lx = __float2bfloat16(v.x - __bfloat162float(hx));
    const __nv_bfloat16 ly = __float2bfloat16(v.y - __bfloat162float(hy));
    const __nv_bfloat16 lz = __float2bfloat16(v.z - __bfloat162float(hz));
    const __nv_bfloat16 lw = __float2bfloat16(v.w - __bfloat162float(hw));
    hi[2 * i + 0] = __nv_bfloat162(hx, hy);
    hi[2 * i + 1] = __nv_bfloat162(hz, hw);
    lo[2 * i + 0] = __nv_bfloat162(lx, ly);
    lo[2 * i + 1] = __nv_bfloat162(lz, lw);
}

// ---------------- recurrence as a blocked linear scan ----------------
__global__ void recur_chunk_sum(const float* __restrict__ time_decay)
{
    const int idx = blockIdx.x * blockDim.x + threadIdx.x;
    const int m  = idx & (PM - 1);
    const int ch = (idx >> 9) & (NCH - 1);
    const int b  = idx >> 15;
    const float decay = sigmoid_f(time_decay[m]) * 0.9f + 0.1f;
    const float* vp = g_v + ((size_t)(b * PT + ch * CHL)) * PM + m;
    float s = 0.0f;
#pragma unroll 8
    for (int j = 0; j < CHL; j++)
        s = fmaf(s, decay, vp[(size_t)j * PM]);
    g_chsum[(b * NCH + ch) * PM + m] = s;
}

__global__ void recur_prefix(const float* __restrict__ time_decay,
                             const float* __restrict__ mem0,
                             float* __restrict__ next_mem)
{
    const int idx = blockIdx.x * blockDim.x + threadIdx.x;
    const int m = idx & (PM - 1);
    const int b = idx >> 9;
    const float decay = sigmoid_f(time_decay[m]) * 0.9f + 0.1f;
    float A = decay;
#pragma unroll
    for (int i = 0; i < 6; i++) A = A * A;   // decay^64
    float P = mem0[b * PM + m];
#pragma unroll 4
    for (int ch = 0; ch < NCH; ch++) {
        g_prefix[(b * NCH + ch) * PM + m] = P;
        P = fmaf(P, A, g_chsum[(b * NCH + ch) * PM + m]);
    }
    if (next_mem) next_mem[b * PM + m] = P;
}

__global__ void recur_emit(const float* __restrict__ time_decay,
                           const float* __restrict__ time_first)
{
    const int idx = blockIdx.x * blockDim.x + threadIdx.x;
    const int m  = idx & (PM - 1);
    const int ch = (idx >> 9) & (NCH - 1);
    const int b  = idx >> 15;
    const float decay = sigmoid_f(time_decay[m]) * 0.9f + 0.1f;
    const float first = sigmoid_f(time_first[m]);
    const size_t base = ((size_t)(b * PT + ch * CHL)) * PM + m;
    const float* vp = g_v + base;
    float s = g_prefix[(b * NCH + ch) * PM + m];
#pragma unroll 8
    for (int j = 0; j < CHL; j++) {
        const float v = vp[(size_t)j * PM];
        const float wvv = fmaf(s, first, v);
        const __nv_bfloat16 h = __float2bfloat16(wvv);
        g_wvh[base + (size_t)j * PM] = h;
        g_wvl[base + (size_t)j * PM] = __float2bfloat16(wvv - __bfloat162float(h));
        s = fmaf(s, decay, v);
    }
}

// ---------------- launch ----------------
extern "C" void kernel_launch(void* const* d_in, const int* in_sizes, int n_in,
                              void* d_out, int out_size)
{
    const float* x    = (const float*)d_in[0];   // [B, T, D]
    const float* mem0 = (const float*)d_in[1];   // [B, M]
    const float* Wv   = (const float*)d_in[2];   // [M, D]
    const float* bv   = (const float*)d_in[3];   // [M]
    const float* Wg   = (const float*)d_in[4];   // [D, D+M]
    const float* bg   = (const float*)d_in[5];   // [D]
    const float* td   = (const float*)d_in[6];   // [M]
    const float* tf   = (const float*)d_in[7];   // [M]
    float* out = (float*)d_out;

    void *pv, *pxh, *pxl, *pwvh, *pwvl, *pWvh, *pWvl, *pWgh, *pWgl;
    cudaGetSymbolAddress(&pv,   g_v);
    cudaGetSymbolAddress(&pxh,  g_xh);
    cudaGetSymbolAddress(&pxl,  g_xl);
    cudaGetSymbolAddress(&pwvh, g_wvh);
    cudaGetSymbolAddress(&pwvl, g_wvl);
    cudaGetSymbolAddress(&pWvh, g_Wvh);
    cudaGetSymbolAddress(&pWvl, g_Wvl);
    cudaGetSymbolAddress(&pWgh, g_Wgh);
    cudaGetSymbolAddress(&pWgl, g_Wgl);

    cudaFuncSetAttribute(gemm_mma, cudaFuncAttributeMaxDynamicSharedMemorySize, SMEM_TOTAL);

    // fp32 -> bf16 hi/lo splits
    {
        int n4 = (PBT * PD) / 4;   // x
        split_fp32<<<(n4 + 255) / 256, 256>>>((const float4*)x,
            (__nv_bfloat162*)pxh, (__nv_bfloat162*)pxl, n4);
        n4 = (PM * PD) / 4;        // Wv
        split_fp32<<<(n4 + 255) / 256, 256>>>((const float4*)Wv,
            (__nv_bfloat162*)pWvh, (__nv_bfloat162*)pWvl, n4);
        n4 = (PD * PKG) / 4;       // Wg
        split_fp32<<<(n4 + 255) / 256, 256>>>((const float4*)Wg,
            (__nv_bfloat162*)pWgh, (__nv_bfloat162*)pWgl, n4);
    }

    // GEMM1: v[BT, M] = x . Wv^T + bv   (tensor cores, split-bf16)
    {
        dim3 grid(PM / 128, PBT / 128);   // (4, 128)
        gemm_mma<<<grid, 256, SMEM_TOTAL>>>(
            (const __nv_bfloat16*)pxh, (const __nv_bfloat16*)pxl, PD,
            nullptr, nullptr, 0,
            (const __nv_bfloat16*)pWvh, (const __nv_bfloat16*)pWvl,
            bv, nullptr, (float*)pv);
    }

    // Recurrence (blocked scan); emit wv directly as bf16 hi/lo
    recur_chunk_sum<<<(PB * NCH * PM) / 256, 256>>>(td);
    float* next_mem = nullptr;
    if (out_size >= (int)((size_t)PBT * PD + (size_t)PB * PM))
        next_mem = out + (size_t)PBT * PD;
    recur_prefix<<<(PB * PM) / 256, 256>>>(td, mem0, next_mem);
    recur_emit<<<(PB * NCH * PM) / 256, 256>>>(td, tf);

    // GEMM2: out[BT, D] = x + [x | wv] . Wg^T + bg
    {
        dim3 grid(PD / 128, PBT / 128);   // (16, 128)
        gemm_mma<<<grid, 256, SMEM_TOTAL>>>(
            (const __nv_bfloat16*)pxh, (const __nv_bfloat16*)pxl, PD,
            (const __nv_bfloat16*)pwvh, (const __nv_bfloat16*)pwvl, PM,
            (const __nv_bfloat16*)pWgh, (const __nv_bfloat16*)pWgl,
            bg, x, out);
    }
}